// round 13
// baseline (speedup 1.0000x reference)
#include <cuda_runtime.h>
#include <cuda_bf16.h>
#include <cstdint>

#define BATCH 2
#define CDIM  512
#define CQK   64
#define NDIM  4096

// projection GEMM tile config: BM=BN=128, BK=64, 256 threads
#define BM  128
#define BN  128
#define BK  64
#define ROWB 128                    // bytes per smem row (64 bf16, swizzled)
#define A_BYTES (BM * ROWB)         // 16384
#define STAGE_B (A_BYTES + BN*ROWB) // 32768
#define STAGES 3
#define SMEM_BYTES (STAGES * STAGE_B)  // 98304

// S-strip kernel: Q tile resident + 3-stage K ring
#define S_Q_BYTES 16384
#define S_K_BYTES 16384
#define S_STAGES 3
#define S_SMEM (S_Q_BYTES + S_STAGES * S_K_BYTES)   // 65536

// O-GEMM config: 256 x 128, 8 warps at 64x64 warp tiles, 1 CTA/SM
// One pipeline stage = TWO k-tiles; 2-stage ring; register-level fragment double-buffer.
#define OBM 256
#define O_A_BYTES (OBM * ROWB)          // 32768
#define O_SUB_B (O_A_BYTES + BN*ROWB)   // 49152 per k-tile (V 32K + E 16K)
#define O_STAGE2 (2 * O_SUB_B)          // 98304 per stage (2 k-tiles)
#define O_SMEM (2 * O_STAGE2)           // 196608

// ---------------- scratch (device globals; no allocation allowed) ----------------
__device__ __nv_bfloat16 g_Xt[BATCH][NDIM][CDIM];    // x transposed, bf16
__device__ __nv_bfloat16 g_Wqk[2*CQK][CDIM];         // [wq; wk] bf16
__device__ float         g_bqk[2*CQK];               // [bq; bk]
__device__ __nv_bfloat16 g_Wv[CDIM][CDIM];           // wv bf16
__device__ __nv_bfloat16 g_QK[BATCH][NDIM][2*CQK];   // q|k per token
__device__ __nv_bfloat16 g_V[BATCH][CDIM][NDIM];     // v in [c][n] layout
__device__ __nv_bfloat16 g_A[BATCH][NDIM][NDIM];     // E = exp(S), unnormalized, bf16
__device__ float         g_psum[BATCH][8][NDIM];     // per-strip partial row sums
__device__ float         g_rsum[BATCH][NDIM];        // reciprocal of full row sums

// ---------------- PTX helpers ----------------
__device__ __forceinline__ uint32_t smem_u32(const void* p) {
    return (uint32_t)__cvta_generic_to_shared(p);
}
__device__ __forceinline__ void cp16(uint32_t dst, const void* src) {
    asm volatile("cp.async.cg.shared.global [%0], [%1], 16;\n" :: "r"(dst), "l"(src));
}
__device__ __forceinline__ void cp_commit() { asm volatile("cp.async.commit_group;\n"); }
template<int N> __device__ __forceinline__ void cp_wait() {
    asm volatile("cp.async.wait_group %0;\n" :: "n"(N));
}
__device__ __forceinline__ void ldsm4(uint32_t r[4], uint32_t addr) {
    asm volatile("ldmatrix.sync.aligned.m8n8.x4.shared.b16 {%0,%1,%2,%3}, [%4];\n"
                 : "=r"(r[0]), "=r"(r[1]), "=r"(r[2]), "=r"(r[3]) : "r"(addr));
}
__device__ __forceinline__ void mma16816(float c[4], const uint32_t a[4], const uint32_t b[2]) {
    asm volatile(
        "mma.sync.aligned.m16n8k16.row.col.f32.bf16.bf16.f32 "
        "{%0,%1,%2,%3}, {%4,%5,%6,%7}, {%8,%9}, {%0,%1,%2,%3};\n"
        : "+f"(c[0]), "+f"(c[1]), "+f"(c[2]), "+f"(c[3])
        : "r"(a[0]), "r"(a[1]), "r"(a[2]), "r"(a[3]), "r"(b[0]), "r"(b[1]));
}
__device__ __forceinline__ uint32_t swz(uint32_t off) {
    return off ^ ((off >> 3) & 0x70);
}

// ---------------- 3-stage pipelined GEMM (128x128): C += A[BM,K] * B[BN,K]^T ----------------
__device__ __forceinline__ void gemm_pipe(
    const __nv_bfloat16* __restrict__ Ag, int lda,
    const __nv_bfloat16* __restrict__ Bg, int ldb,
    int Ktiles, float (&acc)[2][8][4])
{
    extern __shared__ __align__(1024) char smem[];
    const uint32_t sbase = smem_u32(smem);
    const int tid  = threadIdx.x;
    const int lane = tid & 31, warp = tid >> 5;
    const int wm = warp >> 1, wn = warp & 1;
    const int lrow = tid >> 3;
    const int lcol = (tid & 7) * 16;

    const int a_r = (lane & 7) + (((lane >> 3) & 1) << 3);
    const int a_c = ((lane >> 4) << 3) * 2;
    const int b_r = (lane & 7) + ((lane >> 4) << 3);
    const int b_c = (((lane >> 3) & 1) << 3) * 2;

    auto load_tile = [&](int stage, int kt) {
        const uint32_t as = sbase + stage * STAGE_B;
        const uint32_t bs = as + A_BYTES;
        const __nv_bfloat16* a = Ag + (size_t)kt * BK;
        const __nv_bfloat16* b = Bg + (size_t)kt * BK;
        #pragma unroll
        for (int i = 0; i < 4; i++) {
            const int r = lrow + i*32;
            cp16(as + swz(r*ROWB + lcol), (const char*)(a + (size_t)r * lda) + lcol);
        }
        #pragma unroll
        for (int i = 0; i < 4; i++) {
            const int r = lrow + i*32;
            cp16(bs + swz(r*ROWB + lcol), (const char*)(b + (size_t)r * ldb) + lcol);
        }
        cp_commit();
    };

    load_tile(0, 0);
    if (Ktiles > 1) load_tile(1, 1);

    for (int kt = 0; kt < Ktiles; kt++) {
        if (kt + 2 <= Ktiles) cp_wait<1>(); else cp_wait<0>();
        __syncthreads();
        if (kt + 2 < Ktiles) load_tile((kt + 2) % STAGES, kt + 2);

        const uint32_t as = sbase + (kt % STAGES) * STAGE_B;
        const uint32_t bs = as + A_BYTES;

        #pragma unroll
        for (int kk = 0; kk < BK; kk += 16) {
            uint32_t af[2][4];
            #pragma unroll
            for (int mi = 0; mi < 2; mi++) {
                const int row = wm*32 + mi*16 + a_r;
                ldsm4(af[mi], as + swz(row*ROWB + kk*2 + a_c));
            }
            uint32_t bfr[4][4];
            #pragma unroll
            for (int nj = 0; nj < 4; nj++) {
                const int row = wn*64 + nj*16 + b_r;
                ldsm4(bfr[nj], bs + swz(row*ROWB + kk*2 + b_c));
            }
            #pragma unroll
            for (int mi = 0; mi < 2; mi++)
                #pragma unroll
                for (int nj = 0; nj < 4; nj++) {
                    mma16816(acc[mi][2*nj  ], af[mi], &bfr[nj][0]);
                    mma16816(acc[mi][2*nj+1], af[mi], &bfr[nj][2]);
                }
        }
    }
}

// ---------------- kernel 1: transpose+convert x -> Xt bf16 ----------------
__global__ void k_convert_x(const float* __restrict__ x) {
    __shared__ float tile[32][33];
    const int b  = blockIdx.z;
    const int n0 = blockIdx.x * 32, c0 = blockIdx.y * 32;
    const int tx = threadIdx.x, ty = threadIdx.y;   // (32, 8)
    #pragma unroll
    for (int i = 0; i < 32; i += 8)
        tile[ty + i][tx] = x[((size_t)(b*CDIM + c0 + ty + i)) * NDIM + n0 + tx];
    __syncthreads();
    #pragma unroll
    for (int i = 0; i < 32; i += 8)
        g_Xt[b][n0 + ty + i][c0 + tx] = __float2bfloat16(tile[tx][ty + i]);
}

// ---------------- kernel 2: convert weights/biases ----------------
__global__ void k_convert_w(const float* __restrict__ wq, const float* __restrict__ wk,
                            const float* __restrict__ wv,
                            const float* __restrict__ bq, const float* __restrict__ bk) {
    const int idx = blockIdx.x * 256 + threadIdx.x;
    if (idx < 32768) {
        ((__nv_bfloat16*)g_Wqk)[idx] = __float2bfloat16(wq[idx]);
    } else if (idx < 65536) {
        ((__nv_bfloat16*)g_Wqk)[idx] = __float2bfloat16(wk[idx - 32768]);
    } else if (idx < 65536 + 262144) {
        ((__nv_bfloat16*)g_Wv)[idx - 65536] = __float2bfloat16(wv[idx - 65536]);
    } else if (idx < 65536 + 262144 + 64) {
        g_bqk[idx - 327680] = bq[idx - 327680];
    } else if (idx < 65536 + 262144 + 128) {
        g_bqk[idx - 327680] = bk[idx - 327680 - 64];
    }
}

// ---------------- kernel 3: QK projection ----------------
__global__ void __launch_bounds__(256, 2) k_gemm_qk() {
    const int b = blockIdx.z, m0 = blockIdx.y * BM;
    float acc[2][8][4] = {};
    gemm_pipe(&g_Xt[b][m0][0], CDIM, &g_Wqk[0][0], CDIM, CDIM / BK, acc);

    const int lane = threadIdx.x & 31, warp = threadIdx.x >> 5;
    const int wm = warp >> 1, wn = warp & 1, r = lane >> 2, q = lane & 3;
    #pragma unroll
    for (int mi = 0; mi < 2; mi++)
        #pragma unroll
        for (int ni = 0; ni < 8; ni++) {
            const int m = m0 + wm*32 + mi*16 + r;
            const int n = wn*64 + ni*8 + 2*q;
            const float b0 = g_bqk[n], b1 = g_bqk[n + 1];
            *(__nv_bfloat162*)&g_QK[b][m    ][n] = __floats2bfloat162_rn(acc[mi][ni][0] + b0, acc[mi][ni][1] + b1);
            *(__nv_bfloat162*)&g_QK[b][m + 8][n] = __floats2bfloat162_rn(acc[mi][ni][2] + b0, acc[mi][ni][3] + b1);
        }
}

// ---------------- kernel 4: V projection ----------------
__global__ void __launch_bounds__(256, 2) k_gemm_v(const float* __restrict__ bv) {
    const int b = blockIdx.z, m0 = blockIdx.y * BM, n0 = blockIdx.x * BN;
    float acc[2][8][4] = {};
    gemm_pipe(&g_Wv[m0][0], CDIM, &g_Xt[b][n0][0], CDIM, CDIM / BK, acc);

    const int lane = threadIdx.x & 31, warp = threadIdx.x >> 5;
    const int wm = warp >> 1, wn = warp & 1, r = lane >> 2, q = lane & 3;
    #pragma unroll
    for (int mi = 0; mi < 2; mi++) {
        const int m = m0 + wm*32 + mi*16 + r;
        const float bm0 = bv[m], bm8 = bv[m + 8];
        #pragma unroll
        for (int ni = 0; ni < 8; ni++) {
            const int n = n0 + wn*64 + ni*8 + 2*q;
            *(__nv_bfloat162*)&g_V[b][m    ][n] = __floats2bfloat162_rn(acc[mi][ni][0] + bm0, acc[mi][ni][1] + bm0);
            *(__nv_bfloat162*)&g_V[b][m + 8][n] = __floats2bfloat162_rn(acc[mi][ni][2] + bm8, acc[mi][ni][3] + bm8);
        }
    }
}

// ---------------- kernel 5: S strip  E[i][j]=exp(q_i.k_j) for 128 i x 512 j, + partial sums ----
__global__ void __launch_bounds__(256, 2) k_gemm_s() {
    extern __shared__ __align__(1024) char smem[];
    __shared__ float s_part[2][128];
    const uint32_t sbase = smem_u32(smem);
    const int tid  = threadIdx.x;
    const int lane = tid & 31, warp = tid >> 5;
    const int wm = warp >> 1, wn = warp & 1;
    const int b = blockIdx.z, i0 = blockIdx.y * 128, j0 = blockIdx.x * 512;
    const int r = lane >> 2, q = lane & 3;
    const int lrow = tid >> 3;
    const int lcol = (tid & 7) * 16;
    const int a_r = (lane & 7) + (((lane >> 3) & 1) << 3);
    const int a_c = ((lane >> 4) << 3) * 2;
    const int b_r = (lane & 7) + ((lane >> 4) << 3);
    const int b_c = (((lane >> 3) & 1) << 3) * 2;

    const __nv_bfloat16* Qg = &g_QK[b][i0][0];     // q = first 128 B of each 256 B row
    const __nv_bfloat16* Kg = &g_QK[b][j0][CQK];   // k = second 128 B

    auto load_k = [&](int stage, int jt) {
        const uint32_t ks = sbase + S_Q_BYTES + stage * S_K_BYTES;
        #pragma unroll
        for (int i = 0; i < 4; i++) {
            const int row = lrow + i*32;
            cp16(ks + swz(row*ROWB + lcol),
                 (const char*)(Kg + (size_t)(jt*128 + row) * 128) + lcol);
        }
        cp_commit();
    };

    // Q tile (uncommitted cps fold into the first K commit group)
    #pragma unroll
    for (int i = 0; i < 4; i++) {
        const int row = lrow + i*32;
        cp16(sbase + swz(row*ROWB + lcol), (const char*)(Qg + (size_t)row * 128) + lcol);
    }
    load_k(0, 0);
    load_k(1, 1);

    float rs[2][2] = {};
    for (int jt = 0; jt < 4; jt++) {
        if (jt + 2 <= 4) cp_wait<1>(); else cp_wait<0>();
        __syncthreads();
        if (jt + 2 < 4) load_k((jt + 2) % S_STAGES, jt + 2);

        const uint32_t ks = sbase + S_Q_BYTES + (jt % S_STAGES) * S_K_BYTES;
        float acc[2][8][4] = {};
        #pragma unroll
        for (int kk = 0; kk < 4; kk++) {
            uint32_t af[2][4];
            #pragma unroll
            for (int mi = 0; mi < 2; mi++)
                ldsm4(af[mi], sbase + swz((wm*32 + mi*16 + a_r)*ROWB + kk*32 + a_c));
            uint32_t bf4[4][4];
            #pragma unroll
            for (int nj = 0; nj < 4; nj++)
                ldsm4(bf4[nj], ks + swz((wn*64 + nj*16 + b_r)*ROWB + kk*32 + b_c));
            #pragma unroll
            for (int mi = 0; mi < 2; mi++)
                #pragma unroll
                for (int nj = 0; nj < 4; nj++) {
                    mma16816(acc[mi][2*nj  ], af[mi], &bf4[nj][0]);
                    mma16816(acc[mi][2*nj+1], af[mi], &bf4[nj][2]);
                }
        }
        // exp + store E + accumulate row sums
        #pragma unroll
        for (int mi = 0; mi < 2; mi++)
            #pragma unroll
            for (int ni = 0; ni < 8; ni++) {
                const int m = i0 + wm*32 + mi*16 + r;
                const int n = j0 + jt*128 + wn*64 + ni*8 + 2*q;
                const float e0 = __expf(acc[mi][ni][0]);
                const float e1 = __expf(acc[mi][ni][1]);
                const float e2 = __expf(acc[mi][ni][2]);
                const float e3 = __expf(acc[mi][ni][3]);
                *(__nv_bfloat162*)&g_A[b][m    ][n] = __floats2bfloat162_rn(e0, e1);
                *(__nv_bfloat162*)&g_A[b][m + 8][n] = __floats2bfloat162_rn(e2, e3);
                rs[mi][0] += e0 + e1;
                rs[mi][1] += e2 + e3;
            }
    }

    #pragma unroll
    for (int mi = 0; mi < 2; mi++)
        #pragma unroll
        for (int h = 0; h < 2; h++) {
            rs[mi][h] += __shfl_xor_sync(0xffffffffu, rs[mi][h], 1);
            rs[mi][h] += __shfl_xor_sync(0xffffffffu, rs[mi][h], 2);
        }
    if (q == 0) {
        #pragma unroll
        for (int mi = 0; mi < 2; mi++)
            #pragma unroll
            for (int h = 0; h < 2; h++)
                s_part[wn][wm*32 + mi*16 + h*8 + r] = rs[mi][h];
    }
    __syncthreads();
    if (tid < 128)
        g_psum[b][blockIdx.x][i0 + tid] = s_part[0][tid] + s_part[1][tid];
}

// ---------------- kernel 5b: fold partial row sums -> reciprocal ----------------
__global__ void k_rowsum() {
    const int id = blockIdx.x * 256 + threadIdx.x;   // 0..8191
    const int b = id / NDIM, m = id % NDIM;
    float s = 0.f;
    #pragma unroll
    for (int t = 0; t < 8; t++) s += g_psum[b][t][m];
    g_rsum[b][m] = 1.0f / s;
}

// ---------------- kernel 6: O-GEMM (256x128, 2 k-tiles/stage, 2-stage ring,
//                  register fragment double-buffer)  out = gm*rinv_n*(V E^T)+x ----
__global__ void __launch_bounds__(256, 1) k_gemm_o(const float* __restrict__ xin,
                                                   const float* __restrict__ gma,
                                                   float* __restrict__ out) {
    extern __shared__ __align__(1024) char smem[];
    const uint32_t sbase = smem_u32(smem);
    const int tid  = threadIdx.x;
    const int lane = tid & 31, warp = tid >> 5;
    const int wm = warp >> 1, wn = warp & 1;          // 4m x 2n, warp tile 64x64
    const int b = blockIdx.z, m0 = blockIdx.y * OBM, n0 = blockIdx.x * BN;
    const int Kt2 = NDIM / (2 * BK);                  // 32 double-k-tiles

    const __nv_bfloat16* Vg = &g_V[b][m0][0];
    const __nv_bfloat16* Eg = &g_A[b][n0][0];

    const int lrow = tid >> 3;
    const int lcol = (tid & 7) * 16;
    const int a_r = (lane & 7) + (((lane >> 3) & 1) << 3);
    const int a_c = ((lane >> 4) << 3) * 2;
    const int b_r = (lane & 7) + ((lane >> 4) << 3);
    const int b_c = (((lane >> 3) & 1) << 3) * 2;

    // one stage = two k-tiles (sub 0/1); ONE commit per stage
    auto load_stage = [&](int stage, int kt2) {
        #pragma unroll
        for (int sub = 0; sub < 2; sub++) {
            const uint32_t vs = sbase + stage * O_STAGE2 + sub * O_SUB_B;
            const uint32_t es = vs + O_A_BYTES;
            const int kt = 2*kt2 + sub;
            const __nv_bfloat16* v = Vg + (size_t)kt * BK;
            const __nv_bfloat16* e = Eg + (size_t)kt * BK;
            #pragma unroll
            for (int i = 0; i < 8; i++) {
                const int r = lrow + i*32;
                cp16(vs + swz(r*ROWB + lcol), (const char*)(v + (size_t)r * NDIM) + lcol);
            }
            #pragma unroll
            for (int i = 0; i < 4; i++) {
                const int r = lrow + i*32;
                cp16(es + swz(r*ROWB + lcol), (const char*)(e + (size_t)r * NDIM) + lcol);
            }
        }
        cp_commit();
    };

    float acc[4][8][4] = {};
    uint32_t af[2][4][4], bfr[2][4][4];   // ping-pong fragment buffers

    load_stage(0, 0);

    for (int kt2 = 0; kt2 < Kt2; kt2++) {
        cp_wait<0>();                 // stage kt2's load complete
        __syncthreads();              // + all warps done with the buffer being overwritten
        if (kt2 + 1 < Kt2) load_stage((kt2 + 1) & 1, kt2 + 1);

        const uint32_t stg = sbase + (kt2 & 1) * O_STAGE2;

        // 8 kk-chunks per stage (sub-major); chunk c = sub (c>>2), kk = (c&3)*16
        auto ldfrag = [&](int c, int buf) {
            const uint32_t vs = stg + (c >> 2) * O_SUB_B;
            const uint32_t es = vs + O_A_BYTES;
            const int kkb = (c & 3) * 32;   // byte offset = kk*2
            #pragma unroll
            for (int mi = 0; mi < 4; mi++)
                ldsm4(af[buf][mi], vs + swz((wm*64 + mi*16 + a_r)*ROWB + kkb + a_c));
            #pragma unroll
            for (int nj = 0; nj < 4; nj++)
                ldsm4(bfr[buf][nj], es + swz((wn*64 + nj*16 + b_r)*ROWB + kkb + b_c));
        };

        ldfrag(0, 0);
        #pragma unroll
        for (int c = 0; c < 8; c++) {
            if (c < 7) ldfrag(c + 1, (c + 1) & 1);   // prefetch next chunk's fragments
            const int buf = c & 1;
            #pragma unroll
            for (int mi = 0; mi < 4; mi++)
                #pragma unroll
                for (int nj = 0; nj < 4; nj++) {
                    mma16816(acc[mi][2*nj  ], af[buf][mi], &bfr[buf][nj][0]);
                    mma16816(acc[mi][2*nj+1], af[buf][mi], &bfr[buf][nj][2]);
                }
        }
    }

    const float gm = gma[0];
    const int r = lane >> 2, q = lane & 3;
    #pragma unroll
    for (int ni = 0; ni < 8; ni++) {
        const int n = n0 + wn*64 + ni*8 + 2*q;
        const float sc0 = gm * g_rsum[b][n];
        const float sc1 = gm * g_rsum[b][n + 1];
        #pragma unroll
        for (int mi = 0; mi < 4; mi++) {
            const int m = m0 + wm*64 + mi*16 + r;
            const size_t i0 = ((size_t)(b*CDIM + m)) * NDIM + n;
            const size_t i8 = i0 + (size_t)8 * NDIM;
            float2 x0 = *(const float2*)&xin[i0];
            float2 x8 = *(const float2*)&xin[i8];
            *(float2*)&out[i0] = make_float2(sc0 * acc[mi][ni][0] + x0.x, sc1 * acc[mi][ni][1] + x0.y);
            *(float2*)&out[i8] = make_float2(sc0 * acc[mi][ni][2] + x8.x, sc1 * acc[mi][ni][3] + x8.y);
        }
    }
}

// ---------------- launch: capture-legal fork (side stream forked FROM stream 0) ----------------
extern "C" void kernel_launch(void* const* d_in, const int* in_sizes, int n_in,
                              void* d_out, int out_size) {
    const float* x  = (const float*)d_in[0];
    // d_in[1] = s (unused by the reference)
    const float* wq = (const float*)d_in[2];
    const float* bq = (const float*)d_in[3];
    const float* wk = (const float*)d_in[4];
    const float* bk = (const float*)d_in[5];
    const float* wv = (const float*)d_in[6];
    const float* bv = (const float*)d_in[7];
    const float* gm = (const float*)d_in[8];
    float* out = (float*)d_out;

    cudaFuncSetAttribute(k_gemm_qk, cudaFuncAttributeMaxDynamicSharedMemorySize, SMEM_BYTES);
    cudaFuncSetAttribute(k_gemm_v,  cudaFuncAttributeMaxDynamicSharedMemorySize, SMEM_BYTES);
    cudaFuncSetAttribute(k_gemm_s,  cudaFuncAttributeMaxDynamicSharedMemorySize, S_SMEM);
    cudaFuncSetAttribute(k_gemm_o,  cudaFuncAttributeMaxDynamicSharedMemorySize, O_SMEM);

    cudaStream_t sv;
    cudaStreamCreateWithFlags(&sv, cudaStreamNonBlocking);
    cudaEvent_t eFork, eX, eW, eV;
    cudaEventCreateWithFlags(&eFork, cudaEventDisableTiming);
    cudaEventCreateWithFlags(&eX, cudaEventDisableTiming);
    cudaEventCreateWithFlags(&eW, cudaEventDisableTiming);
    cudaEventCreateWithFlags(&eV, cudaEventDisableTiming);

    // fork point on the capture (origin) stream — REQUIRED before any sv work
    cudaEventRecord(eFork, 0);
    cudaStreamWaitEvent(sv, eFork, 0);

    // side stream: weight convert, then V projection (needs Wv + Xt)
    k_convert_w<<<1281, 256, 0, sv>>>(wq, wk, wv, bq, bk);
    cudaEventRecord(eW, sv);

    // main stream: x transpose/convert (concurrent with convert_w)
    k_convert_x<<<dim3(128, 16, 2), dim3(32, 8)>>>(x);
    cudaEventRecord(eX, 0);

    cudaStreamWaitEvent(sv, eX, 0);
    k_gemm_v<<<dim3(32, 4, 2), 256, SMEM_BYTES, sv>>>(bv);
    cudaEventRecord(eV, sv);

    // main: QK projection (needs Wqk from sv + Xt), S strips, rowsum
    cudaStreamWaitEvent(0, eW, 0);
    k_gemm_qk<<<dim3(1, 32, 2), 256, SMEM_BYTES>>>();
    k_gemm_s <<<dim3(8, 32, 2), 256, S_SMEM>>>();
    k_rowsum <<<32, 256>>>();

    // join: O needs V (sv), E, rowsum
    cudaStreamWaitEvent(0, eV, 0);
    k_gemm_o <<<dim3(32, 2, 2), 256, O_SMEM>>>(x, gm, out);
}

// round 14
// speedup vs baseline: 1.0251x; 1.0251x over previous
#include <cuda_runtime.h>
#include <cuda_bf16.h>
#include <cstdint>

#define BATCH 2
#define CDIM  512
#define CQK   64
#define NDIM  4096

// projection GEMM tile config: BM=BN=128, BK=64, 256 threads
#define BM  128
#define BN  128
#define BK  64
#define ROWB 128                    // bytes per smem row (64 bf16, swizzled)
#define A_BYTES (BM * ROWB)         // 16384
#define STAGE_B (A_BYTES + BN*ROWB) // 32768
#define STAGES 3
#define SMEM_BYTES (STAGES * STAGE_B)  // 98304

// S-strip kernel: Q tile resident + 3-stage K ring
#define S_Q_BYTES 16384
#define S_K_BYTES 16384
#define S_STAGES 3
#define S_SMEM (S_Q_BYTES + S_STAGES * S_K_BYTES)   // 65536

// ---------------- scratch (device globals; no allocation allowed) ----------------
__device__ __nv_bfloat16 g_Xt[BATCH][NDIM][CDIM];    // x transposed, bf16
__device__ __nv_bfloat16 g_Wqk[2*CQK][CDIM];         // [wq; wk] bf16
__device__ float         g_bqk[2*CQK];               // [bq; bk]
__device__ __nv_bfloat16 g_Wv[CDIM][CDIM];           // wv bf16
__device__ __nv_bfloat16 g_QK[BATCH][NDIM][2*CQK];   // q|k per token
__device__ __nv_bfloat16 g_V[BATCH][CDIM][NDIM];     // v in [c][n] layout
__device__ __nv_bfloat16 g_A[BATCH][NDIM][NDIM];     // E = exp(S), unnormalized, bf16
__device__ float         g_psum[BATCH][8][NDIM];     // per-strip partial row sums
__device__ float         g_rsum[BATCH][NDIM];        // reciprocal of full row sums

// ---------------- PTX helpers ----------------
__device__ __forceinline__ uint32_t smem_u32(const void* p) {
    return (uint32_t)__cvta_generic_to_shared(p);
}
__device__ __forceinline__ void cp16(uint32_t dst, const void* src) {
    asm volatile("cp.async.cg.shared.global [%0], [%1], 16;\n" :: "r"(dst), "l"(src));
}
__device__ __forceinline__ void cp_commit() { asm volatile("cp.async.commit_group;\n"); }
template<int N> __device__ __forceinline__ void cp_wait() {
    asm volatile("cp.async.wait_group %0;\n" :: "n"(N));
}
__device__ __forceinline__ void ldsm4(uint32_t r[4], uint32_t addr) {
    asm volatile("ldmatrix.sync.aligned.m8n8.x4.shared.b16 {%0,%1,%2,%3}, [%4];\n"
                 : "=r"(r[0]), "=r"(r[1]), "=r"(r[2]), "=r"(r[3]) : "r"(addr));
}
__device__ __forceinline__ void mma16816(float c[4], const uint32_t a[4], const uint32_t b[2]) {
    asm volatile(
        "mma.sync.aligned.m16n8k16.row.col.f32.bf16.bf16.f32 "
        "{%0,%1,%2,%3}, {%4,%5,%6,%7}, {%8,%9}, {%0,%1,%2,%3};\n"
        : "+f"(c[0]), "+f"(c[1]), "+f"(c[2]), "+f"(c[3])
        : "r"(a[0]), "r"(a[1]), "r"(a[2]), "r"(a[3]), "r"(b[0]), "r"(b[1]));
}
__device__ __forceinline__ uint32_t swz(uint32_t off) {
    return off ^ ((off >> 3) & 0x70);
}

// ---------------- 3-stage pipelined GEMM (128x128): C += A[BM,K] * B[BN,K]^T ----------------
__device__ __forceinline__ void gemm_pipe(
    const __nv_bfloat16* __restrict__ Ag, int lda,
    const __nv_bfloat16* __restrict__ Bg, int ldb,
    int Ktiles, float (&acc)[2][8][4])
{
    extern __shared__ __align__(1024) char smem[];
    const uint32_t sbase = smem_u32(smem);
    const int tid  = threadIdx.x;
    const int lane = tid & 31, warp = tid >> 5;
    const int wm = warp >> 1, wn = warp & 1;
    const int lrow = tid >> 3;
    const int lcol = (tid & 7) * 16;

    const int a_r = (lane & 7) + (((lane >> 3) & 1) << 3);
    const int a_c = ((lane >> 4) << 3) * 2;
    const int b_r = (lane & 7) + ((lane >> 4) << 3);
    const int b_c = (((lane >> 3) & 1) << 3) * 2;

    auto load_tile = [&](int stage, int kt) {
        const uint32_t as = sbase + stage * STAGE_B;
        const uint32_t bs = as + A_BYTES;
        const __nv_bfloat16* a = Ag + (size_t)kt * BK;
        const __nv_bfloat16* b = Bg + (size_t)kt * BK;
        #pragma unroll
        for (int i = 0; i < 4; i++) {
            const int r = lrow + i*32;
            cp16(as + swz(r*ROWB + lcol), (const char*)(a + (size_t)r * lda) + lcol);
        }
        #pragma unroll
        for (int i = 0; i < 4; i++) {
            const int r = lrow + i*32;
            cp16(bs + swz(r*ROWB + lcol), (const char*)(b + (size_t)r * ldb) + lcol);
        }
        cp_commit();
    };

    load_tile(0, 0);
    if (Ktiles > 1) load_tile(1, 1);

    for (int kt = 0; kt < Ktiles; kt++) {
        if (kt + 2 <= Ktiles) cp_wait<1>(); else cp_wait<0>();
        __syncthreads();
        if (kt + 2 < Ktiles) load_tile((kt + 2) % STAGES, kt + 2);

        const uint32_t as = sbase + (kt % STAGES) * STAGE_B;
        const uint32_t bs = as + A_BYTES;

        #pragma unroll
        for (int kk = 0; kk < BK; kk += 16) {
            uint32_t af[2][4];
            #pragma unroll
            for (int mi = 0; mi < 2; mi++) {
                const int row = wm*32 + mi*16 + a_r;
                ldsm4(af[mi], as + swz(row*ROWB + kk*2 + a_c));
            }
            uint32_t bfr[4][4];
            #pragma unroll
            for (int nj = 0; nj < 4; nj++) {
                const int row = wn*64 + nj*16 + b_r;
                ldsm4(bfr[nj], bs + swz(row*ROWB + kk*2 + b_c));
            }
            #pragma unroll
            for (int mi = 0; mi < 2; mi++)
                #pragma unroll
                for (int nj = 0; nj < 4; nj++) {
                    mma16816(acc[mi][2*nj  ], af[mi], &bfr[nj][0]);
                    mma16816(acc[mi][2*nj+1], af[mi], &bfr[nj][2]);
                }
        }
    }
}

// ---------------- kernel 1: transpose+convert x -> Xt bf16 ----------------
__global__ void k_convert_x(const float* __restrict__ x) {
    __shared__ float tile[32][33];
    const int b  = blockIdx.z;
    const int n0 = blockIdx.x * 32, c0 = blockIdx.y * 32;
    const int tx = threadIdx.x, ty = threadIdx.y;   // (32, 8)
    #pragma unroll
    for (int i = 0; i < 32; i += 8)
        tile[ty + i][tx] = x[((size_t)(b*CDIM + c0 + ty + i)) * NDIM + n0 + tx];
    __syncthreads();
    #pragma unroll
    for (int i = 0; i < 32; i += 8)
        g_Xt[b][n0 + ty + i][c0 + tx] = __float2bfloat16(tile[tx][ty + i]);
}

// ---------------- kernel 2: convert weights/biases ----------------
__global__ void k_convert_w(const float* __restrict__ wq, const float* __restrict__ wk,
                            const float* __restrict__ wv,
                            const float* __restrict__ bq, const float* __restrict__ bk) {
    const int idx = blockIdx.x * 256 + threadIdx.x;
    if (idx < 32768) {
        ((__nv_bfloat16*)g_Wqk)[idx] = __float2bfloat16(wq[idx]);
    } else if (idx < 65536) {
        ((__nv_bfloat16*)g_Wqk)[idx] = __float2bfloat16(wk[idx - 32768]);
    } else if (idx < 65536 + 262144) {
        ((__nv_bfloat16*)g_Wv)[idx - 65536] = __float2bfloat16(wv[idx - 65536]);
    } else if (idx < 65536 + 262144 + 64) {
        g_bqk[idx - 327680] = bq[idx - 327680];
    } else if (idx < 65536 + 262144 + 128) {
        g_bqk[idx - 327680] = bk[idx - 327680 - 64];
    }
}

// ---------------- kernel 3: QK projection ----------------
__global__ void __launch_bounds__(256, 2) k_gemm_qk() {
    const int b = blockIdx.z, m0 = blockIdx.y * BM;
    float acc[2][8][4] = {};
    gemm_pipe(&g_Xt[b][m0][0], CDIM, &g_Wqk[0][0], CDIM, CDIM / BK, acc);

    const int lane = threadIdx.x & 31, warp = threadIdx.x >> 5;
    const int wm = warp >> 1, wn = warp & 1, r = lane >> 2, q = lane & 3;
    #pragma unroll
    for (int mi = 0; mi < 2; mi++)
        #pragma unroll
        for (int ni = 0; ni < 8; ni++) {
            const int m = m0 + wm*32 + mi*16 + r;
            const int n = wn*64 + ni*8 + 2*q;
            const float b0 = g_bqk[n], b1 = g_bqk[n + 1];
            *(__nv_bfloat162*)&g_QK[b][m    ][n] = __floats2bfloat162_rn(acc[mi][ni][0] + b0, acc[mi][ni][1] + b1);
            *(__nv_bfloat162*)&g_QK[b][m + 8][n] = __floats2bfloat162_rn(acc[mi][ni][2] + b0, acc[mi][ni][3] + b1);
        }
}

// ---------------- kernel 4: V projection ----------------
__global__ void __launch_bounds__(256, 2) k_gemm_v(const float* __restrict__ bv) {
    const int b = blockIdx.z, m0 = blockIdx.y * BM, n0 = blockIdx.x * BN;
    float acc[2][8][4] = {};
    gemm_pipe(&g_Wv[m0][0], CDIM, &g_Xt[b][n0][0], CDIM, CDIM / BK, acc);

    const int lane = threadIdx.x & 31, warp = threadIdx.x >> 5;
    const int wm = warp >> 1, wn = warp & 1, r = lane >> 2, q = lane & 3;
    #pragma unroll
    for (int mi = 0; mi < 2; mi++) {
        const int m = m0 + wm*32 + mi*16 + r;
        const float bm0 = bv[m], bm8 = bv[m + 8];
        #pragma unroll
        for (int ni = 0; ni < 8; ni++) {
            const int n = n0 + wn*64 + ni*8 + 2*q;
            *(__nv_bfloat162*)&g_V[b][m    ][n] = __floats2bfloat162_rn(acc[mi][ni][0] + bm0, acc[mi][ni][1] + bm0);
            *(__nv_bfloat162*)&g_V[b][m + 8][n] = __floats2bfloat162_rn(acc[mi][ni][2] + bm8, acc[mi][ni][3] + bm8);
        }
    }
}

// ---------------- kernel 5: S strip  E[i][j]=exp(q_i.k_j) for 128 i x 512 j, + partial sums ----
__global__ void __launch_bounds__(256, 2) k_gemm_s() {
    extern __shared__ __align__(1024) char smem[];
    __shared__ float s_part[2][128];
    const uint32_t sbase = smem_u32(smem);
    const int tid  = threadIdx.x;
    const int lane = tid & 31, warp = tid >> 5;
    const int wm = warp >> 1, wn = warp & 1;
    const int b = blockIdx.z, i0 = blockIdx.y * 128, j0 = blockIdx.x * 512;
    const int r = lane >> 2, q = lane & 3;
    const int lrow = tid >> 3;
    const int lcol = (tid & 7) * 16;
    const int a_r = (lane & 7) + (((lane >> 3) & 1) << 3);
    const int a_c = ((lane >> 4) << 3) * 2;
    const int b_r = (lane & 7) + ((lane >> 4) << 3);
    const int b_c = (((lane >> 3) & 1) << 3) * 2;

    const __nv_bfloat16* Qg = &g_QK[b][i0][0];     // q = first 128 B of each 256 B row
    const __nv_bfloat16* Kg = &g_QK[b][j0][CQK];   // k = second 128 B

    auto load_k = [&](int stage, int jt) {
        const uint32_t ks = sbase + S_Q_BYTES + stage * S_K_BYTES;
        #pragma unroll
        for (int i = 0; i < 4; i++) {
            const int row = lrow + i*32;
            cp16(ks + swz(row*ROWB + lcol),
                 (const char*)(Kg + (size_t)(jt*128 + row) * 128) + lcol);
        }
        cp_commit();
    };

    // Q tile (uncommitted cps fold into the first K commit group)
    #pragma unroll
    for (int i = 0; i < 4; i++) {
        const int row = lrow + i*32;
        cp16(sbase + swz(row*ROWB + lcol), (const char*)(Qg + (size_t)row * 128) + lcol);
    }
    load_k(0, 0);
    load_k(1, 1);

    float rs[2][2] = {};
    for (int jt = 0; jt < 4; jt++) {
        if (jt + 2 <= 4) cp_wait<1>(); else cp_wait<0>();
        __syncthreads();
        if (jt + 2 < 4) load_k((jt + 2) % S_STAGES, jt + 2);

        const uint32_t ks = sbase + S_Q_BYTES + (jt % S_STAGES) * S_K_BYTES;
        float acc[2][8][4] = {};
        #pragma unroll
        for (int kk = 0; kk < 4; kk++) {
            uint32_t af[2][4];
            #pragma unroll
            for (int mi = 0; mi < 2; mi++)
                ldsm4(af[mi], sbase + swz((wm*32 + mi*16 + a_r)*ROWB + kk*32 + a_c));
            uint32_t bf4[4][4];
            #pragma unroll
            for (int nj = 0; nj < 4; nj++)
                ldsm4(bf4[nj], ks + swz((wn*64 + nj*16 + b_r)*ROWB + kk*32 + b_c));
            #pragma unroll
            for (int mi = 0; mi < 2; mi++)
                #pragma unroll
                for (int nj = 0; nj < 4; nj++) {
                    mma16816(acc[mi][2*nj  ], af[mi], &bf4[nj][0]);
                    mma16816(acc[mi][2*nj+1], af[mi], &bf4[nj][2]);
                }
        }
        // exp + store E + accumulate row sums
        #pragma unroll
        for (int mi = 0; mi < 2; mi++)
            #pragma unroll
            for (int ni = 0; ni < 8; ni++) {
                const int m = i0 + wm*32 + mi*16 + r;
                const int n = j0 + jt*128 + wn*64 + ni*8 + 2*q;
                const float e0 = __expf(acc[mi][ni][0]);
                const float e1 = __expf(acc[mi][ni][1]);
                const float e2 = __expf(acc[mi][ni][2]);
                const float e3 = __expf(acc[mi][ni][3]);
                *(__nv_bfloat162*)&g_A[b][m    ][n] = __floats2bfloat162_rn(e0, e1);
                *(__nv_bfloat162*)&g_A[b][m + 8][n] = __floats2bfloat162_rn(e2, e3);
                rs[mi][0] += e0 + e1;
                rs[mi][1] += e2 + e3;
            }
    }

    #pragma unroll
    for (int mi = 0; mi < 2; mi++)
        #pragma unroll
        for (int h = 0; h < 2; h++) {
            rs[mi][h] += __shfl_xor_sync(0xffffffffu, rs[mi][h], 1);
            rs[mi][h] += __shfl_xor_sync(0xffffffffu, rs[mi][h], 2);
        }
    if (q == 0) {
        #pragma unroll
        for (int mi = 0; mi < 2; mi++)
            #pragma unroll
            for (int h = 0; h < 2; h++)
                s_part[wn][wm*32 + mi*16 + h*8 + r] = rs[mi][h];
    }
    __syncthreads();
    if (tid < 128)
        g_psum[b][blockIdx.x][i0 + tid] = s_part[0][tid] + s_part[1][tid];
}

// ---------------- kernel 5b: fold partial row sums -> reciprocal ----------------
__global__ void k_rowsum() {
    const int id = blockIdx.x * 256 + threadIdx.x;   // 0..8191
    const int b = id / NDIM, m = id % NDIM;
    float s = 0.f;
    #pragma unroll
    for (int t = 0; t < 8; t++) s += g_psum[b][t][m];
    g_rsum[b][m] = 1.0f / s;
}

// ---------------- kernel 6: O-GEMM (128x128, 2 CTA/SM, 3-stage)  out = gm*rinv_n*(V E^T)+x ----
__global__ void __launch_bounds__(256, 2) k_gemm_o(const float* __restrict__ xin,
                                                   const float* __restrict__ gma,
                                                   float* __restrict__ out) {
    const int b = blockIdx.z, m0 = blockIdx.y * BM, n0 = blockIdx.x * BN;
    float acc[2][8][4] = {};
    gemm_pipe(&g_V[b][m0][0], NDIM, &g_A[b][n0][0], NDIM, NDIM / BK, acc);

    const float gm = gma[0];
    const int lane = threadIdx.x & 31, warp = threadIdx.x >> 5;
    const int wm = warp >> 1, wn = warp & 1, r = lane >> 2, q = lane & 3;
    #pragma unroll
    for (int ni = 0; ni < 8; ni++) {
        const int n = n0 + wn*64 + ni*8 + 2*q;
        const float sc0 = gm * g_rsum[b][n];
        const float sc1 = gm * g_rsum[b][n + 1];
        #pragma unroll
        for (int mi = 0; mi < 2; mi++) {
            const int m = m0 + wm*32 + mi*16 + r;
            const size_t i0 = ((size_t)(b*CDIM + m)) * NDIM + n;
            const size_t i8 = i0 + (size_t)8 * NDIM;
            float2 x0 = *(const float2*)&xin[i0];
            float2 x8 = *(const float2*)&xin[i8];
            *(float2*)&out[i0] = make_float2(sc0 * acc[mi][ni][0] + x0.x, sc1 * acc[mi][ni][1] + x0.y);
            *(float2*)&out[i8] = make_float2(sc0 * acc[mi][ni][2] + x8.x, sc1 * acc[mi][ni][3] + x8.y);
        }
    }
}

// ---------------- launch: capture-legal fork (side stream forked FROM stream 0) ----------------
extern "C" void kernel_launch(void* const* d_in, const int* in_sizes, int n_in,
                              void* d_out, int out_size) {
    const float* x  = (const float*)d_in[0];
    // d_in[1] = s (unused by the reference)
    const float* wq = (const float*)d_in[2];
    const float* bq = (const float*)d_in[3];
    const float* wk = (const float*)d_in[4];
    const float* bk = (const float*)d_in[5];
    const float* wv = (const float*)d_in[6];
    const float* bv = (const float*)d_in[7];
    const float* gm = (const float*)d_in[8];
    float* out = (float*)d_out;

    cudaFuncSetAttribute(k_gemm_qk, cudaFuncAttributeMaxDynamicSharedMemorySize, SMEM_BYTES);
    cudaFuncSetAttribute(k_gemm_v,  cudaFuncAttributeMaxDynamicSharedMemorySize, SMEM_BYTES);
    cudaFuncSetAttribute(k_gemm_s,  cudaFuncAttributeMaxDynamicSharedMemorySize, S_SMEM);
    cudaFuncSetAttribute(k_gemm_o,  cudaFuncAttributeMaxDynamicSharedMemorySize, SMEM_BYTES);

    cudaStream_t sv;
    cudaStreamCreateWithFlags(&sv, cudaStreamNonBlocking);
    cudaEvent_t eFork, eX, eW, eV;
    cudaEventCreateWithFlags(&eFork, cudaEventDisableTiming);
    cudaEventCreateWithFlags(&eX, cudaEventDisableTiming);
    cudaEventCreateWithFlags(&eW, cudaEventDisableTiming);
    cudaEventCreateWithFlags(&eV, cudaEventDisableTiming);

    // fork point on the capture (origin) stream — REQUIRED before any sv work
    cudaEventRecord(eFork, 0);
    cudaStreamWaitEvent(sv, eFork, 0);

    // side stream: weight convert, then V projection (needs Wv + Xt)
    k_convert_w<<<1281, 256, 0, sv>>>(wq, wk, wv, bq, bk);
    cudaEventRecord(eW, sv);

    // main stream: x transpose/convert (concurrent with convert_w)
    k_convert_x<<<dim3(128, 16, 2), dim3(32, 8)>>>(x);
    cudaEventRecord(eX, 0);

    cudaStreamWaitEvent(sv, eX, 0);
    k_gemm_v<<<dim3(32, 4, 2), 256, SMEM_BYTES, sv>>>(bv);
    cudaEventRecord(eV, sv);

    // main: QK projection (needs Wqk from sv + Xt), S strips, rowsum
    cudaStreamWaitEvent(0, eW, 0);
    k_gemm_qk<<<dim3(1, 32, 2), 256, SMEM_BYTES>>>();
    k_gemm_s <<<dim3(8, 32, 2), 256, S_SMEM>>>();
    k_rowsum <<<32, 256>>>();

    // join: O needs V (sv), E, rowsum
    cudaStreamWaitEvent(0, eV, 0);
    k_gemm_o <<<dim3(32, 4, 2), 256, SMEM_BYTES>>>(x, gm, out);
}